// round 12
// baseline (speedup 1.0000x reference)
#include <cuda_runtime.h>
#include <cstdint>

#define N_NODES 50000
#define N_EDGES 600000
#define D 128
#define M_PAD 50048        // 391 * 128
#define SCAN_B 49          // ceil(50000/1024)

// Scratch (__device__ globals; no runtime allocation).
// Pre-split tf32 operand buffers: .x = hi bits, .y = lo bits.
// g_asp pad rows [50000,50048) never written -> BSS zero -> tf32 0.0 (valid).
__device__ uint2 g_asp[(size_t)M_PAD * D];   // split agg
__device__ uint2 g_hsp[(size_t)M_PAD * D];   // split h
__device__ uint2 g_w1sp[D * D];
__device__ uint2 g_w2sp[D * D];
__device__ int g_is64;
__device__ int g_deg[N_NODES];
__device__ int g_psum[N_NODES];
__device__ int g_off[N_NODES];
__device__ int g_cur[N_NODES];
__device__ int g_btot[SCAN_B];
__device__ int g_btot_ex[SCAN_B];
__device__ int g_esrc[N_EDGES];

// ---- tf32 split helpers ----
__device__ __forceinline__ uint32_t f2tf32(float f) {
    uint32_t r;
    asm("cvt.rna.tf32.f32 %0, %1;" : "=r"(r) : "f"(f));
    return r;
}
__device__ __forceinline__ uint2 split2(float f) {
    uint2 r;
    r.x = f2tf32(f);
    r.y = f2tf32(f - __uint_as_float(r.x));
    return r;
}

// ---- edge decode (int32 vs int64 buffers) ----
__device__ __forceinline__ void edge_sd(const int* ei, int e, int& src, int& dst) {
    if (g_is64) {
        src = ei[2 * e];
        dst = ei[2 * (N_EDGES + e)];
    } else {
        src = ei[e];
        dst = ei[N_EDGES + e];
    }
}

__global__ void probe_kernel(const int* __restrict__ ei) {
    __shared__ int nonzero;
    if (threadIdx.x == 0) nonzero = 0;
    __syncthreads();
    for (int i = threadIdx.x; i < 4096; i += blockDim.x)
        if (ei[2 * i + 1] != 0) nonzero = 1;
    __syncthreads();
    if (threadIdx.x == 0) g_is64 = (nonzero == 0) ? 1 : 0;
}

__global__ void zero_deg_kernel() {
    int i = blockIdx.x * blockDim.x + threadIdx.x;
    if (i < N_NODES) g_deg[i] = 0;
}

__global__ void hist_kernel(const int* __restrict__ ei) {
    int e = blockIdx.x * blockDim.x + threadIdx.x;
    if (e >= N_EDGES) return;
    int src, dst;
    edge_sd(ei, e, src, dst);
    if ((unsigned)src >= (unsigned)N_NODES || (unsigned)dst >= (unsigned)N_NODES)
        return;
    atomicAdd(&g_deg[dst], 1);
}

__global__ void __launch_bounds__(1024) scan_block_kernel() {
    __shared__ int s[1024];
    int t = threadIdx.x;
    int i = blockIdx.x * 1024 + t;
    int v = (i < N_NODES) ? g_deg[i] : 0;
    s[t] = v;
    __syncthreads();
#pragma unroll
    for (int d = 1; d < 1024; d <<= 1) {
        int add = (t >= d) ? s[t - d] : 0;
        __syncthreads();
        s[t] += add;
        __syncthreads();
    }
    if (i < N_NODES) g_psum[i] = s[t] - v;
    if (t == 1023) g_btot[blockIdx.x] = s[t];
}

__global__ void scan_tot_kernel() {
    __shared__ int s[64];
    int t = threadIdx.x;
    int v = (t < SCAN_B) ? g_btot[t] : 0;
    s[t] = v;
    __syncthreads();
#pragma unroll
    for (int d = 1; d < 64; d <<= 1) {
        int add = (t >= d) ? s[t - d] : 0;
        __syncthreads();
        s[t] += add;
        __syncthreads();
    }
    if (t < SCAN_B) g_btot_ex[t] = s[t] - v;
}

__global__ void finalize_off_kernel() {
    int i = blockIdx.x * blockDim.x + threadIdx.x;
    if (i < N_NODES) {
        int o = g_psum[i] + g_btot_ex[i >> 10];
        g_off[i] = o;
        g_cur[i] = o;
    }
}

__global__ void fill_kernel(const int* __restrict__ ei) {
    int e = blockIdx.x * blockDim.x + threadIdx.x;
    if (e >= N_EDGES) return;
    int src, dst;
    edge_sd(ei, e, src, dst);
    if ((unsigned)src >= (unsigned)N_NODES || (unsigned)dst >= (unsigned)N_NODES)
        return;
    int pos = atomicAdd(&g_cur[dst], 1);
    g_esrc[pos] = src;
}

// Split W1 and W2 into tf32 hi/lo pairs.
__global__ void split_w_kernel(const float* __restrict__ W1,
                               const float* __restrict__ W2) {
    int i = blockIdx.x * blockDim.x + threadIdx.x;
    if (i < D * D) {
        g_w1sp[i] = split2(W1[i]);
        g_w2sp[i] = split2(W2[i]);
    }
}

// Warp per node: agg[n] = (1+eps)x[n] + sum x[src]; writes pre-split uint2.
__global__ void gather_kernel(const float4* __restrict__ x,
                              const float* __restrict__ eps) {
    int gid = blockIdx.x * blockDim.x + threadIdx.x;
    int n = gid >> 5;
    int lane = gid & 31;
    if (n >= N_NODES) return;
    float s = 1.0f + __ldg(eps);
    int beg = g_off[n];
    int d = g_deg[n];
    float4 a = x[(long long)n * 32 + lane];
    a.x *= s; a.y *= s; a.z *= s; a.w *= s;
    for (int i = 0; i < d; i++) {
        int src = g_esrc[beg + i];
        float4 v = x[(long long)src * 32 + lane];
        a.x += v.x; a.y += v.y; a.z += v.z; a.w += v.w;
    }
    uint2* o = g_asp + (long long)n * D + lane * 4;
    o[0] = split2(a.x);
    o[1] = split2(a.y);
    o[2] = split2(a.z);
    o[3] = split2(a.w);
}

#define MMA_TF32(c, a, b)                                            \
    asm("mma.sync.aligned.m16n8k8.row.col.f32.tf32.tf32.f32 "        \
        "{%0,%1,%2,%3}, {%4,%5,%6,%7}, {%8,%9}, {%0,%1,%2,%3};"      \
        : "+f"((c)[0]), "+f"((c)[1]), "+f"((c)[2]), "+f"((c)[3])     \
        : "r"((a)[0]), "r"((a)[1]), "r"((a)[2]), "r"((a)[3]),        \
          "r"((b)[0]), "r"((b)[1]))

#define CP_ASYNC16(dst, src)                                         \
    asm volatile("cp.async.cg.shared.global [%0], [%1], 16;" ::      \
        "r"((uint32_t)__cvta_generic_to_shared(dst)), "l"(src))
#define CP_COMMIT()  asm volatile("cp.async.commit_group;" ::: "memory")
#define CP_WAIT(n)   asm volatile("cp.async.wait_group %0;" :: "n"(n) : "memory")

// out = relu(A @ W + bias) on pre-split tf32 operands.
// 128x128 tile, BK=8, 16 k-steps, cp.async double buffer, 8 warps (64x32).
// STORE_SPLIT: 1 -> write uint2 split (h), 0 -> write fp32 (final out).
template <int STORE_SPLIT>
__global__ void __launch_bounds__(256, 2) gemm_relu_sp(
    const uint2* __restrict__ A, const uint2* __restrict__ W,
    const float* __restrict__ bias, void* __restrict__ out, int M_store) {
    // As stride 12 uint2: LDS.64 phase banks (12q + r4) mod 16 distinct.
    // Bs stride 132 uint2: (132 r4 + q) mod 16 = (4 r4 + q) distinct.
    __shared__ uint2 As[2][128][12];
    __shared__ uint2 Bs[2][8][132];

    const int t = threadIdx.x;
    const int lane = t & 31;
    const int wid = t >> 5;
    const int warp_m = wid & 1;
    const int warp_n = wid >> 1;
    const int m0 = blockIdx.x * 128;
    const int q = lane >> 2;
    const int r4 = lane & 3;

    float acc[4][4][4];
#pragma unroll
    for (int i = 0; i < 4; i++)
#pragma unroll
        for (int j = 0; j < 4; j++)
#pragma unroll
            for (int c = 0; c < 4; c++) acc[i][j][c] = 0.0f;

    // tile = 8 k-cols. A: 128x8 uint2 (8KB), B: 8x128 uint2 (8KB).
    auto load_tile = [&](int kc, int b) {
#pragma unroll
        for (int l = 0; l < 2; l++) {
            int j = t + l * 256;          // 0..511
            {   // A: row = j/4, k-pair = (j%4)*2
                int row = j >> 2;
                int kp = (j & 3) * 2;
                CP_ASYNC16(&As[b][row][kp],
                           A + (long long)(m0 + row) * D + kc * 8 + kp);
            }
            {   // B: k-row = j/64, n-pair = (j%64)*2
                int kk = j >> 6;
                int np = (j & 63) * 2;
                CP_ASYNC16(&Bs[b][kk][np],
                           W + (long long)(kc * 8 + kk) * D + np);
            }
        }
    };

    load_tile(0, 0);
    CP_COMMIT();

    for (int kc = 0; kc < 16; kc++) {
        int b = kc & 1;
        if (kc < 15) {
            load_tile(kc + 1, b ^ 1);
            CP_COMMIT();
            CP_WAIT(1);
        } else {
            CP_WAIT(0);
        }
        __syncthreads();

        // one k8 step per tile
        uint32_t ah[4][4], al[4][4];
#pragma unroll
        for (int i = 0; i < 4; i++) {
            int rm = warp_m * 64 + i * 16 + q;
            uint2 a0 = As[b][rm][r4];
            uint2 a1 = As[b][rm + 8][r4];
            uint2 a2 = As[b][rm][r4 + 4];
            uint2 a3 = As[b][rm + 8][r4 + 4];
            ah[i][0] = a0.x; al[i][0] = a0.y;
            ah[i][1] = a1.x; al[i][1] = a1.y;
            ah[i][2] = a2.x; al[i][2] = a2.y;
            ah[i][3] = a3.x; al[i][3] = a3.y;
        }
        uint32_t bh[4][2], bl[4][2];
#pragma unroll
        for (int j = 0; j < 4; j++) {
            int cn = warp_n * 32 + j * 8 + q;
            uint2 b0 = Bs[b][r4][cn];
            uint2 b1 = Bs[b][r4 + 4][cn];
            bh[j][0] = b0.x; bl[j][0] = b0.y;
            bh[j][1] = b1.x; bl[j][1] = b1.y;
        }
#pragma unroll
        for (int i = 0; i < 4; i++)
#pragma unroll
            for (int j = 0; j < 4; j++) {
                MMA_TF32(acc[i][j], ah[i], bh[j]);
                MMA_TF32(acc[i][j], ah[i], bl[j]);
                MMA_TF32(acc[i][j], al[i], bh[j]);
            }
        __syncthreads();
    }

    // Epilogue: bias + relu; store split uint2 (h) or fp32 (final out).
#pragma unroll
    for (int j = 0; j < 4; j++) {
        int col = warp_n * 32 + j * 8 + 2 * r4;
        float bx = __ldg(bias + col);
        float by = __ldg(bias + col + 1);
#pragma unroll
        for (int i = 0; i < 4; i++) {
            int row0 = m0 + warp_m * 64 + i * 16 + q;
            int row1 = row0 + 8;
            float v0 = fmaxf(acc[i][j][0] + bx, 0.0f);
            float v1 = fmaxf(acc[i][j][1] + by, 0.0f);
            float v2 = fmaxf(acc[i][j][2] + bx, 0.0f);
            float v3 = fmaxf(acc[i][j][3] + by, 0.0f);
            if (STORE_SPLIT) {
                uint2* o = (uint2*)out;
                if (row0 < M_store) {
                    o[(long long)row0 * D + col] = split2(v0);
                    o[(long long)row0 * D + col + 1] = split2(v1);
                }
                if (row1 < M_store) {
                    o[(long long)row1 * D + col] = split2(v2);
                    o[(long long)row1 * D + col + 1] = split2(v3);
                }
            } else {
                float* o = (float*)out;
                if (row0 < M_store)
                    *(float2*)(o + (long long)row0 * D + col) =
                        make_float2(v0, v1);
                if (row1 < M_store)
                    *(float2*)(o + (long long)row1 * D + col) =
                        make_float2(v2, v3);
            }
        }
    }
}

extern "C" void kernel_launch(void* const* d_in, const int* in_sizes, int n_in,
                              void* d_out, int out_size) {
    const float* x = (const float*)d_in[0];
    const int* ei = (const int*)d_in[1];
    const float* W1 = (const float*)d_in[2];
    const float* b1 = (const float*)d_in[3];
    const float* W2 = (const float*)d_in[4];
    const float* b2 = (const float*)d_in[5];
    const float* eps = (const float*)d_in[6];

    static uint2* asp = nullptr;
    static uint2* hsp = nullptr;
    static uint2* w1sp = nullptr;
    static uint2* w2sp = nullptr;
    if (!asp) {
        cudaGetSymbolAddress((void**)&asp, g_asp);
        cudaGetSymbolAddress((void**)&hsp, g_hsp);
        cudaGetSymbolAddress((void**)&w1sp, g_w1sp);
        cudaGetSymbolAddress((void**)&w2sp, g_w2sp);
    }

    const int EB = (N_EDGES + 255) / 256;

    probe_kernel<<<1, 256>>>(ei);
    zero_deg_kernel<<<(N_NODES + 255) / 256, 256>>>();
    hist_kernel<<<EB, 256>>>(ei);
    scan_block_kernel<<<SCAN_B, 1024>>>();
    scan_tot_kernel<<<1, 64>>>();
    finalize_off_kernel<<<(N_NODES + 255) / 256, 256>>>();
    fill_kernel<<<EB, 256>>>(ei);
    split_w_kernel<<<(D * D + 255) / 256, 256>>>(W1, W2);
    gather_kernel<<<(N_NODES * 32 + 255) / 256, 256>>>((const float4*)x, eps);

    gemm_relu_sp<1><<<M_PAD / 128, 256>>>(asp, w1sp, b1, hsp, M_PAD);
    gemm_relu_sp<0><<<M_PAD / 128, 256>>>(hsp, w2sp, b2, d_out, N_NODES);
}

// round 13
// speedup vs baseline: 1.1905x; 1.1905x over previous
#include <cuda_runtime.h>
#include <cstdint>

#define N_NODES 50000
#define N_EDGES 600000
#define D 128
#define M_PAD 50048        // 391 * 128
#define SCAN_B 49          // ceil(50000/1024)

// Scratch (__device__ globals; no runtime allocation).
// g_agg pad rows [50000,50048) never written -> stay BSS-zero (deterministic).
__device__ float g_agg[(size_t)M_PAD * D];
__device__ int g_is64;
__device__ int g_deg[N_NODES];
__device__ int g_psum[N_NODES];
__device__ int g_off[N_NODES];
__device__ int g_cur[N_NODES];
__device__ int g_btot[SCAN_B];
__device__ int g_btot_ex[SCAN_B];
__device__ int g_esrc[N_EDGES];

// ---- edge decode (int32 vs int64 buffers) ----
__device__ __forceinline__ void edge_sd(const int* ei, int e, int& src, int& dst) {
    if (g_is64) {
        src = ei[2 * e];
        dst = ei[2 * (N_EDGES + e)];
    } else {
        src = ei[e];
        dst = ei[N_EDGES + e];
    }
}

__global__ void probe_kernel(const int* __restrict__ ei) {
    __shared__ int nonzero;
    if (threadIdx.x == 0) nonzero = 0;
    __syncthreads();
    for (int i = threadIdx.x; i < 4096; i += blockDim.x)
        if (ei[2 * i + 1] != 0) nonzero = 1;
    __syncthreads();
    if (threadIdx.x == 0) g_is64 = (nonzero == 0) ? 1 : 0;
}

__global__ void zero_deg_kernel() {
    int i = blockIdx.x * blockDim.x + threadIdx.x;
    if (i < N_NODES) g_deg[i] = 0;
}

__global__ void hist_kernel(const int* __restrict__ ei) {
    int e = blockIdx.x * blockDim.x + threadIdx.x;
    if (e >= N_EDGES) return;
    int src, dst;
    edge_sd(ei, e, src, dst);
    if ((unsigned)src >= (unsigned)N_NODES || (unsigned)dst >= (unsigned)N_NODES)
        return;
    atomicAdd(&g_deg[dst], 1);
}

__global__ void __launch_bounds__(1024) scan_block_kernel() {
    __shared__ int s[1024];
    int t = threadIdx.x;
    int i = blockIdx.x * 1024 + t;
    int v = (i < N_NODES) ? g_deg[i] : 0;
    s[t] = v;
    __syncthreads();
#pragma unroll
    for (int d = 1; d < 1024; d <<= 1) {
        int add = (t >= d) ? s[t - d] : 0;
        __syncthreads();
        s[t] += add;
        __syncthreads();
    }
    if (i < N_NODES) g_psum[i] = s[t] - v;
    if (t == 1023) g_btot[blockIdx.x] = s[t];
}

__global__ void scan_tot_kernel() {
    __shared__ int s[64];
    int t = threadIdx.x;
    int v = (t < SCAN_B) ? g_btot[t] : 0;
    s[t] = v;
    __syncthreads();
#pragma unroll
    for (int d = 1; d < 64; d <<= 1) {
        int add = (t >= d) ? s[t - d] : 0;
        __syncthreads();
        s[t] += add;
        __syncthreads();
    }
    if (t < SCAN_B) g_btot_ex[t] = s[t] - v;
}

__global__ void finalize_off_kernel() {
    int i = blockIdx.x * blockDim.x + threadIdx.x;
    if (i < N_NODES) {
        int o = g_psum[i] + g_btot_ex[i >> 10];
        g_off[i] = o;
        g_cur[i] = o;
    }
}

__global__ void fill_kernel(const int* __restrict__ ei) {
    int e = blockIdx.x * blockDim.x + threadIdx.x;
    if (e >= N_EDGES) return;
    int src, dst;
    edge_sd(ei, e, src, dst);
    if ((unsigned)src >= (unsigned)N_NODES || (unsigned)dst >= (unsigned)N_NODES)
        return;
    int pos = atomicAdd(&g_cur[dst], 1);
    g_esrc[pos] = src;
}

// Warp per node: agg[n] = (1+eps)x[n] + sum x[src]; fp32 writes.
__global__ void gather_kernel(const float4* __restrict__ x,
                              const float* __restrict__ eps) {
    int gid = blockIdx.x * blockDim.x + threadIdx.x;
    int n = gid >> 5;
    int lane = gid & 31;
    if (n >= N_NODES) return;
    float s = 1.0f + __ldg(eps);
    int beg = g_off[n];
    int d = g_deg[n];
    float4 a = x[(long long)n * 32 + lane];
    a.x *= s; a.y *= s; a.z *= s; a.w *= s;
    for (int i = 0; i < d; i++) {
        int src = g_esrc[beg + i];
        float4 v = x[(long long)src * 32 + lane];
        a.x += v.x; a.y += v.y; a.z += v.z; a.w += v.w;
    }
    ((float4*)g_agg)[(long long)n * 32 + lane] = a;
}

// ---- tf32 / mma / cp.async helpers ----
__device__ __forceinline__ uint32_t f2tf32(float f) {
    uint32_t r;
    asm("cvt.rna.tf32.f32 %0, %1;" : "=r"(r) : "f"(f));
    return r;
}
__device__ __forceinline__ void split_tf32(float f, uint32_t& hi, uint32_t& lo) {
    hi = f2tf32(f);
    lo = f2tf32(f - __uint_as_float(hi));
}

#define MMA_TF32(c, a, b)                                            \
    asm("mma.sync.aligned.m16n8k8.row.col.f32.tf32.tf32.f32 "        \
        "{%0,%1,%2,%3}, {%4,%5,%6,%7}, {%8,%9}, {%0,%1,%2,%3};"      \
        : "+f"((c)[0]), "+f"((c)[1]), "+f"((c)[2]), "+f"((c)[3])     \
        : "r"((a)[0]), "r"((a)[1]), "r"((a)[2]), "r"((a)[3]),        \
          "r"((b)[0]), "r"((b)[1]))

#define CP_ASYNC16(dst, src)                                         \
    asm volatile("cp.async.cg.shared.global [%0], [%1], 16;" ::      \
        "r"((uint32_t)__cvta_generic_to_shared(dst)), "l"(src))
#define CP_COMMIT()  asm volatile("cp.async.commit_group;" ::: "memory")
#define CP_WAIT(n)   asm volatile("cp.async.wait_group %0;" :: "n"(n) : "memory")

// Dynamic smem layout (floats):
//   hs : [128][132]            h tile          offset 0       (67584 B)
//   As : [2][128][20]          agg tiles       offset 16896   (20480 B)
//   Bs : [2][16][136]          W tiles         offset 22016   (17408 B)
#define HS_OFF 0
#define AS_OFF 16896
#define BS_OFF 22016
#define SMEM_BYTES 105472

// Fused MLP: out = relu(relu(agg@W1+b1)@W2+b2), one 128-row tile per CTA.
// Phase 1: R11 GEMM (cp.async dbl-buffer agg+W1 tiles) -> h tile in smem.
// Phase 2: stream W2 tiles; A-frags read from smem h tile. tf32 3-way split.
__global__ void __launch_bounds__(256, 2) fused_mlp_kernel(
    const float* __restrict__ A, const float* __restrict__ W1,
    const float* __restrict__ b1, const float* __restrict__ W2,
    const float* __restrict__ b2, float* __restrict__ out) {
    extern __shared__ float sm[];
    float* hs = sm + HS_OFF;     // [row][132]
    float* As = sm + AS_OFF;     // [b][row][20]
    float* Bs = sm + BS_OFF;     // [b][kk][136]

    const int t = threadIdx.x;
    const int lane = t & 31;
    const int wid = t >> 5;
    const int warp_m = wid & 1;
    const int warp_n = wid >> 1;
    const int m0 = blockIdx.x * 128;
    const int q = lane >> 2;
    const int r4 = lane & 3;

    float acc[4][4][4];
#pragma unroll
    for (int i = 0; i < 4; i++)
#pragma unroll
        for (int j = 0; j < 4; j++)
#pragma unroll
            for (int c = 0; c < 4; c++) acc[i][j][c] = 0.0f;

    // ---- phase-1 tile loader: agg + W1, BK=16 ----
    auto load_tile1 = [&](int kc, int b) {
#pragma unroll
        for (int l = 0; l < 2; l++) {
            int j = t + l * 256;
            {
                int row = j >> 2;
                int k4 = (j & 3) * 4;
                CP_ASYNC16(&As[(b * 128 + row) * 20 + k4],
                           A + (long long)(m0 + row) * D + kc * 16 + k4);
            }
            {
                int kk = j >> 5;
                int c4 = (j & 31) * 4;
                CP_ASYNC16(&Bs[(b * 16 + kk) * 136 + c4],
                           W1 + (long long)(kc * 16 + kk) * D + c4);
            }
        }
    };

    load_tile1(0, 0);
    CP_COMMIT();

    for (int kc = 0; kc < 8; kc++) {
        int b = kc & 1;
        if (kc < 7) {
            load_tile1(kc + 1, b ^ 1);
            CP_COMMIT();
            CP_WAIT(1);
        } else {
            CP_WAIT(0);
        }
        __syncthreads();

#pragma unroll
        for (int kk8 = 0; kk8 < 16; kk8 += 8) {
            int kr = kk8 + r4;
            uint32_t ah[4][4], al[4][4];
#pragma unroll
            for (int i = 0; i < 4; i++) {
                int rm = warp_m * 64 + i * 16 + q;
                split_tf32(As[(b * 128 + rm) * 20 + kr],           ah[i][0], al[i][0]);
                split_tf32(As[(b * 128 + rm + 8) * 20 + kr],       ah[i][1], al[i][1]);
                split_tf32(As[(b * 128 + rm) * 20 + kr + 4],       ah[i][2], al[i][2]);
                split_tf32(As[(b * 128 + rm + 8) * 20 + kr + 4],   ah[i][3], al[i][3]);
            }
            uint32_t bh[4][2], bl[4][2];
#pragma unroll
            for (int j = 0; j < 4; j++) {
                int cn = warp_n * 32 + j * 8 + q;
                split_tf32(Bs[(b * 16 + kr) * 136 + cn],       bh[j][0], bl[j][0]);
                split_tf32(Bs[(b * 16 + kr + 4) * 136 + cn],   bh[j][1], bl[j][1]);
            }
#pragma unroll
            for (int i = 0; i < 4; i++)
#pragma unroll
                for (int j = 0; j < 4; j++) {
                    MMA_TF32(acc[i][j], ah[i], bh[j]);
                    MMA_TF32(acc[i][j], ah[i], bl[j]);
                    MMA_TF32(acc[i][j], al[i], bh[j]);
                }
        }
        __syncthreads();
    }

    // ---- phase-1 epilogue: h tile -> smem (local rows, no guards) ----
#pragma unroll
    for (int j = 0; j < 4; j++) {
        int col = warp_n * 32 + j * 8 + 2 * r4;
        float bx = __ldg(b1 + col);
        float by = __ldg(b1 + col + 1);
#pragma unroll
        for (int i = 0; i < 4; i++) {
            int row0 = warp_m * 64 + i * 16 + q;
            int row1 = row0 + 8;
            *(float2*)(hs + row0 * 132 + col) =
                make_float2(fmaxf(acc[i][j][0] + bx, 0.0f),
                            fmaxf(acc[i][j][1] + by, 0.0f));
            *(float2*)(hs + row1 * 132 + col) =
                make_float2(fmaxf(acc[i][j][2] + bx, 0.0f),
                            fmaxf(acc[i][j][3] + by, 0.0f));
        }
    }
    __syncthreads();   // h tile complete before phase 2 reads it

    // ---- phase 2: acc = h @ W2 ----
#pragma unroll
    for (int i = 0; i < 4; i++)
#pragma unroll
        for (int j = 0; j < 4; j++)
#pragma unroll
            for (int c = 0; c < 4; c++) acc[i][j][c] = 0.0f;

    auto load_tile2 = [&](int kc, int b) {
#pragma unroll
        for (int l = 0; l < 2; l++) {
            int j = t + l * 256;
            int kk = j >> 5;
            int c4 = (j & 31) * 4;
            CP_ASYNC16(&Bs[(b * 16 + kk) * 136 + c4],
                       W2 + (long long)(kc * 16 + kk) * D + c4);
        }
    };

    load_tile2(0, 0);
    CP_COMMIT();

    for (int kc = 0; kc < 8; kc++) {
        int b = kc & 1;
        if (kc < 7) {
            load_tile2(kc + 1, b ^ 1);
            CP_COMMIT();
            CP_WAIT(1);
        } else {
            CP_WAIT(0);
        }
        __syncthreads();

#pragma unroll
        for (int kk8 = 0; kk8 < 16; kk8 += 8) {
            int kr = kc * 16 + kk8 + r4;   // absolute h column
            uint32_t ah[4][4], al[4][4];
#pragma unroll
            for (int i = 0; i < 4; i++) {
                int rm = warp_m * 64 + i * 16 + q;
                split_tf32(hs[rm * 132 + kr],           ah[i][0], al[i][0]);
                split_tf32(hs[(rm + 8) * 132 + kr],     ah[i][1], al[i][1]);
                split_tf32(hs[rm * 132 + kr + 4],       ah[i][2], al[i][2]);
                split_tf32(hs[(rm + 8) * 132 + kr + 4], ah[i][3], al[i][3]);
            }
            int kl = kk8 + r4;
            uint32_t bh[4][2], bl[4][2];
#pragma unroll
            for (int j = 0; j < 4; j++) {
                int cn = warp_n * 32 + j * 8 + q;
                split_tf32(Bs[(b * 16 + kl) * 136 + cn],     bh[j][0], bl[j][0]);
                split_tf32(Bs[(b * 16 + kl + 4) * 136 + cn], bh[j][1], bl[j][1]);
            }
#pragma unroll
            for (int i = 0; i < 4; i++)
#pragma unroll
                for (int j = 0; j < 4; j++) {
                    MMA_TF32(acc[i][j], ah[i], bh[j]);
                    MMA_TF32(acc[i][j], ah[i], bl[j]);
                    MMA_TF32(acc[i][j], al[i], bh[j]);
                }
        }
        __syncthreads();
    }

    // ---- phase-2 epilogue: final out (guarded to N_NODES) ----
#pragma unroll
    for (int j = 0; j < 4; j++) {
        int col = warp_n * 32 + j * 8 + 2 * r4;
        float bx = __ldg(b2 + col);
        float by = __ldg(b2 + col + 1);
#pragma unroll
        for (int i = 0; i < 4; i++) {
            int row0 = m0 + warp_m * 64 + i * 16 + q;
            int row1 = row0 + 8;
            if (row0 < N_NODES)
                *(float2*)(out + (long long)row0 * D + col) =
                    make_float2(fmaxf(acc[i][j][0] + bx, 0.0f),
                                fmaxf(acc[i][j][1] + by, 0.0f));
            if (row1 < N_NODES)
                *(float2*)(out + (long long)row1 * D + col) =
                    make_float2(fmaxf(acc[i][j][2] + bx, 0.0f),
                                fmaxf(acc[i][j][3] + by, 0.0f));
        }
    }
}

extern "C" void kernel_launch(void* const* d_in, const int* in_sizes, int n_in,
                              void* d_out, int out_size) {
    const float* x = (const float*)d_in[0];
    const int* ei = (const int*)d_in[1];
    const float* W1 = (const float*)d_in[2];
    const float* b1 = (const float*)d_in[3];
    const float* W2 = (const float*)d_in[4];
    const float* b2 = (const float*)d_in[5];
    const float* eps = (const float*)d_in[6];
    float* out = (float*)d_out;

    static float* agg = nullptr;
    if (!agg) {
        cudaGetSymbolAddress((void**)&agg, g_agg);
        cudaFuncSetAttribute(fused_mlp_kernel,
                             cudaFuncAttributeMaxDynamicSharedMemorySize,
                             SMEM_BYTES);
    }

    const int EB = (N_EDGES + 255) / 256;

    probe_kernel<<<1, 256>>>(ei);
    zero_deg_kernel<<<(N_NODES + 255) / 256, 256>>>();
    hist_kernel<<<EB, 256>>>(ei);
    scan_block_kernel<<<SCAN_B, 1024>>>();
    scan_tot_kernel<<<1, 64>>>();
    finalize_off_kernel<<<(N_NODES + 255) / 256, 256>>>();
    fill_kernel<<<EB, 256>>>(ei);
    gather_kernel<<<(N_NODES * 32 + 255) / 256, 256>>>((const float4*)x, eps);

    fused_mlp_kernel<<<M_PAD / 128, 256, SMEM_BYTES>>>(agg, W1, b1, W2, b2, out);
}